// round 4
// baseline (speedup 1.0000x reference)
#include <cuda_runtime.h>
#include <cstdint>

// ============================================================================
// CausalAttention, B=4, S=4096, D=1024, fp32 in/out.
// tf32x3-split mma.sync GEMMs, hi/lo pre-split in smem, double-buffered,
// 512 threads/CTA (16 warps, 4x4 warp grid, 32x32 warp tiles).
// ============================================================================

#define BM 128
#define BN 128
#define BK 32

static constexpr int Bb = 4;
static constexpr int S  = 4096;
static constexpr int D  = 1024;

static constexpr int A_WORDS   = BM * BK;          // 4096
static constexpr int B_STRIDE  = BN + 8;           // 136
static constexpr int B_WORDS   = BK * B_STRIDE;    // 4352
static constexpr int STAGE_W   = 2 * A_WORDS + 2 * B_WORDS;   // 16896
static constexpr int SMEM_BYTES = 2 * STAGE_W * 4;            // 135168

static __device__ float g_q [(size_t)Bb * S * D];
static __device__ float g_k [(size_t)Bb * S * D];
static __device__ float g_kt[(size_t)Bb * D * S];
static __device__ float g_v [(size_t)Bb * S * D];
static __device__ float g_s [(size_t)Bb * S * S];

// ---------------------------------------------------------------------------
__device__ __forceinline__ void tf32_split(float x, uint32_t& hi, uint32_t& lo) {
    uint32_t h;
    asm("cvt.rna.tf32.f32 %0, %1;" : "=r"(h) : "f"(x));
    float r = x - __uint_as_float(h);
    uint32_t l;
    asm("cvt.rna.tf32.f32 %0, %1;" : "=r"(l) : "f"(r));
    hi = h; lo = l;
}

__device__ __forceinline__ void mma_tf32(float (&d)[4], const uint32_t (&a)[4],
                                         const uint32_t (&b)[2]) {
    asm volatile(
        "mma.sync.aligned.m16n8k8.row.col.f32.tf32.tf32.f32 "
        "{%0,%1,%2,%3}, {%4,%5,%6,%7}, {%8,%9}, {%0,%1,%2,%3};"
        : "+f"(d[0]), "+f"(d[1]), "+f"(d[2]), "+f"(d[3])
        : "r"(a[0]), "r"(a[1]), "r"(a[2]), "r"(a[3]), "r"(b[0]), "r"(b[1]));
}

__device__ __forceinline__ void cvt_store4(uint32_t* hi, uint32_t* lo, int widx,
                                           float4 v) {
    uint4 h, l;
    tf32_split(v.x, h.x, l.x);
    tf32_split(v.y, h.y, l.y);
    tf32_split(v.z, h.z, l.z);
    tf32_split(v.w, h.w, l.w);
    *(uint4*)(hi + widx) = h;
    *(uint4*)(lo + widx) = l;
}

// ---------------------------------------------------------------------------
// Core: C = A * B, A MxK row-major (lda), B KxN row-major (ldb), C MxN.
// A/B/C already batch-offset. 512 threads.
// ---------------------------------------------------------------------------
template<bool KLIM>
__device__ __forceinline__ void
gemm_core(const float* __restrict__ A, const float* __restrict__ Bm,
          float* __restrict__ C, int N, int K, int lda, int ldb,
          int bm, int bn)
{
    const int kEnd = KLIM ? min(K, (bm + 1) * BM) : K;

    extern __shared__ uint32_t sm[];

    const int tid  = threadIdx.x;
    const int wid  = tid >> 5;
    const int wm   = wid & 3;               // 4 warps along M
    const int wn   = wid >> 2;              // 4 warps along N
    const int lane = tid & 31;
    const int g    = lane >> 2;
    const int c    = lane & 3;

    // staging maps (512 threads)
    const int at_row = tid >> 3;            // 0..63 (+64)
    const int at_col = (tid & 7) * 4;
    const int a_sw   = at_col ^ ((at_row & 7) << 2);
    const int bs_row = tid >> 5;            // 0..15 (+16)
    const int bs_col = (tid & 31) * 4;

    const float* Aptr = A + (long long)(bm * BM + at_row) * lda + at_col;
    const float* Bptr = Bm + (long long)bs_row * ldb + bn * BN + bs_col;

    float4 pa[2], pb[2];
    #pragma unroll
    for (int r = 0; r < 2; r++)
        pa[r] = *(const float4*)(Aptr + (long long)(r * 64) * lda);
    #pragma unroll
    for (int r = 0; r < 2; r++)
        pb[r] = *(const float4*)(Bptr + (long long)(r * 16) * ldb);

    {   // stage 0
        uint32_t* Ah = sm;
        uint32_t* Al = sm + A_WORDS;
        uint32_t* Bh = sm + 2 * A_WORDS;
        uint32_t* Bl = Bh + B_WORDS;
        #pragma unroll
        for (int r = 0; r < 2; r++)
            cvt_store4(Ah, Al, (at_row + r * 64) * BK + a_sw, pa[r]);
        #pragma unroll
        for (int r = 0; r < 2; r++)
            cvt_store4(Bh, Bl, (bs_row + r * 16) * B_STRIDE + bs_col, pb[r]);
    }
    __syncthreads();

    float acc[2][4][4];
    #pragma unroll
    for (int mi = 0; mi < 2; mi++)
        #pragma unroll
        for (int ni = 0; ni < 4; ni++)
            #pragma unroll
            for (int q = 0; q < 4; q++) acc[mi][ni][q] = 0.f;

    int st = 0;
    for (int k0 = 0; k0 < kEnd; k0 += BK) {
        const bool has_next = (k0 + BK) < kEnd;
        if (has_next) {
            #pragma unroll
            for (int r = 0; r < 2; r++)
                pa[r] = *(const float4*)(Aptr + (long long)(r * 64) * lda + (k0 + BK));
            #pragma unroll
            for (int r = 0; r < 2; r++)
                pb[r] = *(const float4*)(Bptr + (long long)(k0 + BK + r * 16) * ldb);
        }

        const uint32_t* Ah = sm + st * STAGE_W;
        const uint32_t* Al = Ah + A_WORDS;
        const uint32_t* Bh = Ah + 2 * A_WORDS;
        const uint32_t* Bl = Bh + B_WORDS;

        #pragma unroll
        for (int kt = 0; kt < 4; kt++) {
            const int x0 = (kt * 8 + c)     ^ (g << 2);
            const int x1 = (kt * 8 + c + 4) ^ (g << 2);
            uint32_t ah[2][4], al[2][4];
            #pragma unroll
            for (int mi = 0; mi < 2; mi++) {
                const int r0 = (wm * 32 + mi * 16 + g) * BK;
                const int r1 = r0 + 8 * BK;
                ah[mi][0] = Ah[r0 + x0];  al[mi][0] = Al[r0 + x0];
                ah[mi][1] = Ah[r1 + x0];  al[mi][1] = Al[r1 + x0];
                ah[mi][2] = Ah[r0 + x1];  al[mi][2] = Al[r0 + x1];
                ah[mi][3] = Ah[r1 + x1];  al[mi][3] = Al[r1 + x1];
            }
            const int br0 = (kt * 8 + c) * B_STRIDE;
            const int br1 = (kt * 8 + c + 4) * B_STRIDE;
            #pragma unroll
            for (int ni = 0; ni < 4; ni++) {
                const int col = wn * 32 + ni * 8 + g;
                uint32_t bh[2], bl[2];
                bh[0] = Bh[br0 + col];  bh[1] = Bh[br1 + col];
                bl[0] = Bl[br0 + col];  bl[1] = Bl[br1 + col];
                #pragma unroll
                for (int mi = 0; mi < 2; mi++) {
                    mma_tf32(acc[mi][ni], ah[mi], bh);
                    mma_tf32(acc[mi][ni], al[mi], bh);
                    mma_tf32(acc[mi][ni], ah[mi], bl);
                }
            }
        }

        if (has_next) {
            uint32_t* nAh = sm + (st ^ 1) * STAGE_W;
            uint32_t* nAl = nAh + A_WORDS;
            uint32_t* nBh = nAh + 2 * A_WORDS;
            uint32_t* nBl = nBh + B_WORDS;
            #pragma unroll
            for (int r = 0; r < 2; r++)
                cvt_store4(nAh, nAl, (at_row + r * 64) * BK + a_sw, pa[r]);
            #pragma unroll
            for (int r = 0; r < 2; r++)
                cvt_store4(nBh, nBl, (bs_row + r * 16) * B_STRIDE + bs_col, pb[r]);
        }
        __syncthreads();
        st ^= 1;
    }

    // epilogue
    #pragma unroll
    for (int mi = 0; mi < 2; mi++) {
        const int r0 = bm * BM + wm * 32 + mi * 16 + g;
        #pragma unroll
        for (int ni = 0; ni < 4; ni++) {
            const int cc = bn * BN + wn * 32 + ni * 8 + c * 2;
            float2 v0 = make_float2(acc[mi][ni][0], acc[mi][ni][1]);
            float2 v1 = make_float2(acc[mi][ni][2], acc[mi][ni][3]);
            *(float2*)(C + (long long)r0 * N + cc)       = v0;
            *(float2*)(C + (long long)(r0 + 8) * N + cc) = v1;
        }
    }
}

// ---- merged QKV projections: blockIdx.z selects (W, out) ------------------
__global__ void __launch_bounds__(512, 1)
gemm_qkv(const float* __restrict__ x,
         const float* __restrict__ Wq, const float* __restrict__ Wk,
         const float* __restrict__ Wv,
         float* __restrict__ q, float* __restrict__ k, float* __restrict__ v)
{
    const float* W;
    float* out;
    if (blockIdx.z == 0)      { W = Wq; out = q; }
    else if (blockIdx.z == 1) { W = Wk; out = k; }
    else                      { W = Wv; out = v; }
    gemm_core<false>(x, W, out, D, D, D, D, blockIdx.y, blockIdx.x);
}

// ---- scores = Q K^T (K^T precomputed, causal block skip) ------------------
__global__ void __launch_bounds__(512, 1)
gemm_scores(const float* __restrict__ q, const float* __restrict__ kt,
            float* __restrict__ sc)
{
    const int bm = blockIdx.y, bn = blockIdx.x;
    if (bn > bm) return;
    const long long z = blockIdx.z;
    gemm_core<false>(q + z * (long long)S * D, kt + z * (long long)D * S,
                     sc + z * (long long)S * S, S, D, D, S, bm, bn);
}

// ---- out = P V (K limited to diagonal block) ------------------------------
__global__ void __launch_bounds__(512, 1)
gemm_pv(const float* __restrict__ sc, const float* __restrict__ v,
        float* __restrict__ out)
{
    const long long z = blockIdx.z;
    gemm_core<true>(sc + z * (long long)S * S, v + z * (long long)S * D,
                    out + z * (long long)S * D, D, S, S, D,
                    blockIdx.y, blockIdx.x);
}

// ---------------------------------------------------------------------------
__global__ void __launch_bounds__(256)
transpose_k(const float* __restrict__ src, float* __restrict__ dst)
{
    __shared__ float t[32][33];
    const int s0 = blockIdx.x << 5;
    const int d0 = blockIdx.y << 5;
    const int tx = threadIdx.x & 31;
    const int ty = threadIdx.x >> 5;
    const float* sp = src + (size_t)blockIdx.z * S * D;
    float*       dp = dst + (size_t)blockIdx.z * D * S;
    #pragma unroll
    for (int i = 0; i < 32; i += 8)
        t[ty + i][tx] = sp[(size_t)(s0 + ty + i) * D + d0 + tx];
    __syncthreads();
    #pragma unroll
    for (int i = 0; i < 32; i += 8)
        dp[(size_t)(d0 + ty + i) * S + s0 + tx] = t[tx][ty + i];
}

// ---------------------------------------------------------------------------
// Causal softmax, 2-pass online, float4 main loops.
// ---------------------------------------------------------------------------
__global__ void __launch_bounds__(256)
softmax_causal(float* __restrict__ sc)
{
    const int r = blockIdx.x;
    const int b = r >> 12;
    const int i = r & (S - 1);
    float* row = sc + ((long long)b * S * S) + ((long long)i * S);
    const int n  = i + 1;
    const int n4 = n & ~3;
    const int tid  = threadIdx.x;
    const int wid  = tid >> 5;
    const int lane = tid & 31;
    const float scale = 0.03125f;   // 1/sqrt(1024)

    __shared__ float shm[8], shs[8];

    auto upd = [&](float& m, float& s, float v) {
        if (v <= m) s += __expf((v - m) * scale);
        else { s = s * __expf((m - v) * scale) + 1.f; m = v; }
    };

    float m = -3.0e38f, s = 0.f;
    for (int j = tid * 4; j < n4; j += 1024) {
        float4 vv = *(const float4*)(row + j);
        upd(m, s, vv.x); upd(m, s, vv.y); upd(m, s, vv.z); upd(m, s, vv.w);
    }
    for (int j = n4 + tid; j < n; j += 256) upd(m, s, row[j]);

    #pragma unroll
    for (int o = 16; o > 0; o >>= 1) {
        float mo = __shfl_xor_sync(0xffffffffu, m, o);
        float so = __shfl_xor_sync(0xffffffffu, s, o);
        float M  = fmaxf(m, mo);
        s = s * __expf((m - M) * scale) + so * __expf((mo - M) * scale);
        m = M;
    }
    if (lane == 0) { shm[wid] = m; shs[wid] = s; }
    __syncthreads();
    float M = shm[0], Sm = shs[0];
    #pragma unroll
    for (int t = 1; t < 8; t++) {
        float mo = shm[t], so = shs[t];
        float Mx = fmaxf(M, mo);
        Sm = Sm * __expf((M - Mx) * scale) + so * __expf((mo - Mx) * scale);
        M = Mx;
    }
    const float inv = 1.0f / Sm;

    for (int j = tid * 4; j < n4; j += 1024) {
        float4 vv = *(const float4*)(row + j);
        vv.x = __expf((vv.x - M) * scale) * inv;
        vv.y = __expf((vv.y - M) * scale) * inv;
        vv.z = __expf((vv.z - M) * scale) * inv;
        vv.w = __expf((vv.w - M) * scale) * inv;
        *(float4*)(row + j) = vv;
    }
    for (int j = n4 + tid; j < n; j += 256)
        row[j] = __expf((row[j] - M) * scale) * inv;

    const int end = ((i >> 7) + 1) << 7;
    for (int j = n + tid; j < end; j += 256) row[j] = 0.f;
}

// ---------------------------------------------------------------------------
extern "C" void kernel_launch(void* const* d_in, const int* in_sizes, int n_in,
                              void* d_out, int out_size)
{
    const float* x  = (const float*)d_in[0];
    const float* Wq = (const float*)d_in[1];
    const float* Wk = (const float*)d_in[2];
    const float* Wv = (const float*)d_in[3];
    float* out = (float*)d_out;

    static float *q = nullptr, *k = nullptr, *kt = nullptr, *v = nullptr,
                 *sc = nullptr;
    static bool init = false;
    if (!init) {
        cudaGetSymbolAddress((void**)&q,  g_q);
        cudaGetSymbolAddress((void**)&k,  g_k);
        cudaGetSymbolAddress((void**)&kt, g_kt);
        cudaGetSymbolAddress((void**)&v,  g_v);
        cudaGetSymbolAddress((void**)&sc, g_s);
        cudaFuncSetAttribute(gemm_qkv,
                             cudaFuncAttributeMaxDynamicSharedMemorySize, SMEM_BYTES);
        cudaFuncSetAttribute(gemm_scores,
                             cudaFuncAttributeMaxDynamicSharedMemorySize, SMEM_BYTES);
        cudaFuncSetAttribute(gemm_pv,
                             cudaFuncAttributeMaxDynamicSharedMemorySize, SMEM_BYTES);
        init = true;
    }

    // 1) QKV projections (merged, z = which projection)
    gemm_qkv<<<dim3(D / BN, (Bb * S) / BM, 3), 512, SMEM_BYTES>>>(
        x, Wq, Wk, Wv, q, k, v);

    // 2) K -> K^T
    transpose_k<<<dim3(S / 32, D / 32, Bb), 256>>>(k, kt);

    // 3) scores = Q K^T
    gemm_scores<<<dim3(S / BN, S / BM, Bb), 512, SMEM_BYTES>>>(q, kt, sc);

    // 4) softmax
    softmax_causal<<<Bb * S, 256>>>(sc);

    // 5) out = P @ V
    gemm_pv<<<dim3(D / BN, S / BM, Bb), 512, SMEM_BYTES>>>(sc, v, out);
}

// round 5
// speedup vs baseline: 1.0048x; 1.0048x over previous
#include <cuda_runtime.h>
#include <cstdint>

// ============================================================================
// CausalAttention, B=4, S=4096, D=1024, fp32 in/out.
// tf32x3-split mma.sync GEMMs, hi/lo pre-split in smem, double-buffered,
// 512 threads/CTA. MMAs issued grouped-by-term so consecutive tensor ops hit
// distinct accumulators (no RAW serialization); asm is non-volatile so ptxas
// may schedule freely.
// ============================================================================

#define BM 128
#define BN 128
#define BK 32

static constexpr int Bb = 4;
static constexpr int S  = 4096;
static constexpr int D  = 1024;

static constexpr int A_WORDS   = BM * BK;          // 4096
static constexpr int B_STRIDE  = BN + 8;           // 136
static constexpr int B_WORDS   = BK * B_STRIDE;    // 4352
static constexpr int STAGE_W   = 2 * A_WORDS + 2 * B_WORDS;   // 16896
static constexpr int SMEM_BYTES = 2 * STAGE_W * 4;            // 135168

static __device__ float g_q [(size_t)Bb * S * D];
static __device__ float g_k [(size_t)Bb * S * D];
static __device__ float g_kt[(size_t)Bb * D * S];
static __device__ float g_v [(size_t)Bb * S * D];
static __device__ float g_s [(size_t)Bb * S * S];

// ---------------------------------------------------------------------------
__device__ __forceinline__ void tf32_split(float x, uint32_t& hi, uint32_t& lo) {
    uint32_t h;
    asm("cvt.rna.tf32.f32 %0, %1;" : "=r"(h) : "f"(x));
    float r = x - __uint_as_float(h);
    uint32_t l;
    asm("cvt.rna.tf32.f32 %0, %1;" : "=r"(l) : "f"(r));
    hi = h; lo = l;
}

// NOTE: non-volatile on purpose — lets ptxas interleave independent MMAs.
__device__ __forceinline__ void mma_tf32(float (&d)[4], const uint32_t (&a)[4],
                                         const uint32_t (&b)[2]) {
    asm("mma.sync.aligned.m16n8k8.row.col.f32.tf32.tf32.f32 "
        "{%0,%1,%2,%3}, {%4,%5,%6,%7}, {%8,%9}, {%0,%1,%2,%3};"
        : "+f"(d[0]), "+f"(d[1]), "+f"(d[2]), "+f"(d[3])
        : "r"(a[0]), "r"(a[1]), "r"(a[2]), "r"(a[3]), "r"(b[0]), "r"(b[1]));
}

__device__ __forceinline__ void cvt_store4(uint32_t* hi, uint32_t* lo, int widx,
                                           float4 v) {
    uint4 h, l;
    tf32_split(v.x, h.x, l.x);
    tf32_split(v.y, h.y, l.y);
    tf32_split(v.z, h.z, l.z);
    tf32_split(v.w, h.w, l.w);
    *(uint4*)(hi + widx) = h;
    *(uint4*)(lo + widx) = l;
}

// ---------------------------------------------------------------------------
// Core: C = A * B, A MxK row-major (lda), B KxN row-major (ldb), C MxN.
// A/B/C already batch-offset. 512 threads, 4x4 warp grid, 32x32 warp tiles.
// ---------------------------------------------------------------------------
template<bool KLIM>
__device__ __forceinline__ void
gemm_core(const float* __restrict__ A, const float* __restrict__ Bm,
          float* __restrict__ C, int N, int K, int lda, int ldb,
          int bm, int bn)
{
    const int kEnd = KLIM ? min(K, (bm + 1) * BM) : K;

    extern __shared__ uint32_t sm[];

    const int tid  = threadIdx.x;
    const int wid  = tid >> 5;
    const int wm   = wid & 3;
    const int wn   = wid >> 2;
    const int lane = tid & 31;
    const int g    = lane >> 2;
    const int c    = lane & 3;

    const int at_row = tid >> 3;
    const int at_col = (tid & 7) * 4;
    const int a_sw   = at_col ^ ((at_row & 7) << 2);
    const int bs_row = tid >> 5;
    const int bs_col = (tid & 31) * 4;

    const float* Aptr = A + (long long)(bm * BM + at_row) * lda + at_col;
    const float* Bptr = Bm + (long long)bs_row * ldb + bn * BN + bs_col;

    float4 pa[2], pb[2];
    #pragma unroll
    for (int r = 0; r < 2; r++)
        pa[r] = *(const float4*)(Aptr + (long long)(r * 64) * lda);
    #pragma unroll
    for (int r = 0; r < 2; r++)
        pb[r] = *(const float4*)(Bptr + (long long)(r * 16) * ldb);

    {   // stage 0
        uint32_t* Ah = sm;
        uint32_t* Al = sm + A_WORDS;
        uint32_t* Bh = sm + 2 * A_WORDS;
        uint32_t* Bl = Bh + B_WORDS;
        #pragma unroll
        for (int r = 0; r < 2; r++)
            cvt_store4(Ah, Al, (at_row + r * 64) * BK + a_sw, pa[r]);
        #pragma unroll
        for (int r = 0; r < 2; r++)
            cvt_store4(Bh, Bl, (bs_row + r * 16) * B_STRIDE + bs_col, pb[r]);
    }
    __syncthreads();

    float acc[2][4][4];
    #pragma unroll
    for (int mi = 0; mi < 2; mi++)
        #pragma unroll
        for (int ni = 0; ni < 4; ni++)
            #pragma unroll
            for (int q = 0; q < 4; q++) acc[mi][ni][q] = 0.f;

    int st = 0;
    for (int k0 = 0; k0 < kEnd; k0 += BK) {
        const bool has_next = (k0 + BK) < kEnd;
        if (has_next) {
            #pragma unroll
            for (int r = 0; r < 2; r++)
                pa[r] = *(const float4*)(Aptr + (long long)(r * 64) * lda + (k0 + BK));
            #pragma unroll
            for (int r = 0; r < 2; r++)
                pb[r] = *(const float4*)(Bptr + (long long)(k0 + BK + r * 16) * ldb);
        }

        const uint32_t* Ah = sm + st * STAGE_W;
        const uint32_t* Al = Ah + A_WORDS;
        const uint32_t* Bh = Ah + 2 * A_WORDS;
        const uint32_t* Bl = Bh + B_WORDS;

        #pragma unroll
        for (int kt = 0; kt < 4; kt++) {
            const int x0 = (kt * 8 + c)     ^ (g << 2);
            const int x1 = (kt * 8 + c + 4) ^ (g << 2);

            // ---- load ALL fragments for this kt
            uint32_t ah[2][4], al[2][4];
            #pragma unroll
            for (int mi = 0; mi < 2; mi++) {
                const int r0 = (wm * 32 + mi * 16 + g) * BK;
                const int r1 = r0 + 8 * BK;
                ah[mi][0] = Ah[r0 + x0];  al[mi][0] = Al[r0 + x0];
                ah[mi][1] = Ah[r1 + x0];  al[mi][1] = Al[r1 + x0];
                ah[mi][2] = Ah[r0 + x1];  al[mi][2] = Al[r0 + x1];
                ah[mi][3] = Ah[r1 + x1];  al[mi][3] = Al[r1 + x1];
            }
            const int br0 = (kt * 8 + c) * B_STRIDE;
            const int br1 = (kt * 8 + c + 4) * B_STRIDE;
            uint32_t bh[4][2], bl[4][2];
            #pragma unroll
            for (int ni = 0; ni < 4; ni++) {
                const int col = wn * 32 + ni * 8 + g;
                bh[ni][0] = Bh[br0 + col];  bh[ni][1] = Bh[br1 + col];
                bl[ni][0] = Bl[br0 + col];  bl[ni][1] = Bl[br1 + col];
            }

            // ---- issue grouped by split term: consecutive MMAs hit
            //      DISTINCT accumulators -> no RAW serialization.
            #pragma unroll
            for (int mi = 0; mi < 2; mi++)
                #pragma unroll
                for (int ni = 0; ni < 4; ni++)
                    mma_tf32(acc[mi][ni], ah[mi], bh[ni]);
            #pragma unroll
            for (int mi = 0; mi < 2; mi++)
                #pragma unroll
                for (int ni = 0; ni < 4; ni++)
                    mma_tf32(acc[mi][ni], al[mi], bh[ni]);
            #pragma unroll
            for (int mi = 0; mi < 2; mi++)
                #pragma unroll
                for (int ni = 0; ni < 4; ni++)
                    mma_tf32(acc[mi][ni], ah[mi], bl[ni]);
        }

        if (has_next) {
            uint32_t* nAh = sm + (st ^ 1) * STAGE_W;
            uint32_t* nAl = nAh + A_WORDS;
            uint32_t* nBh = nAh + 2 * A_WORDS;
            uint32_t* nBl = nBh + B_WORDS;
            #pragma unroll
            for (int r = 0; r < 2; r++)
                cvt_store4(nAh, nAl, (at_row + r * 64) * BK + a_sw, pa[r]);
            #pragma unroll
            for (int r = 0; r < 2; r++)
                cvt_store4(nBh, nBl, (bs_row + r * 16) * B_STRIDE + bs_col, pb[r]);
        }
        __syncthreads();
        st ^= 1;
    }

    // epilogue
    #pragma unroll
    for (int mi = 0; mi < 2; mi++) {
        const int r0 = bm * BM + wm * 32 + mi * 16 + g;
        #pragma unroll
        for (int ni = 0; ni < 4; ni++) {
            const int cc = bn * BN + wn * 32 + ni * 8 + c * 2;
            float2 v0 = make_float2(acc[mi][ni][0], acc[mi][ni][1]);
            float2 v1 = make_float2(acc[mi][ni][2], acc[mi][ni][3]);
            *(float2*)(C + (long long)r0 * N + cc)       = v0;
            *(float2*)(C + (long long)(r0 + 8) * N + cc) = v1;
        }
    }
}

// ---- merged QKV projections ----------------------------------------------
__global__ void __launch_bounds__(512, 1)
gemm_qkv(const float* __restrict__ x,
         const float* __restrict__ Wq, const float* __restrict__ Wk,
         const float* __restrict__ Wv,
         float* __restrict__ q, float* __restrict__ k, float* __restrict__ v)
{
    const float* W;
    float* out;
    if (blockIdx.z == 0)      { W = Wq; out = q; }
    else if (blockIdx.z == 1) { W = Wk; out = k; }
    else                      { W = Wv; out = v; }
    gemm_core<false>(x, W, out, D, D, D, D, blockIdx.y, blockIdx.x);
}

// ---- scores = Q K^T -------------------------------------------------------
__global__ void __launch_bounds__(512, 1)
gemm_scores(const float* __restrict__ q, const float* __restrict__ kt,
            float* __restrict__ sc)
{
    const int bm = blockIdx.y, bn = blockIdx.x;
    if (bn > bm) return;
    const long long z = blockIdx.z;
    gemm_core<false>(q + z * (long long)S * D, kt + z * (long long)D * S,
                     sc + z * (long long)S * S, S, D, D, S, bm, bn);
}

// ---- out = P V ------------------------------------------------------------
__global__ void __launch_bounds__(512, 1)
gemm_pv(const float* __restrict__ sc, const float* __restrict__ v,
        float* __restrict__ out)
{
    const long long z = blockIdx.z;
    gemm_core<true>(sc + z * (long long)S * S, v + z * (long long)S * D,
                    out + z * (long long)S * D, D, S, S, D,
                    blockIdx.y, blockIdx.x);
}

// ---------------------------------------------------------------------------
__global__ void __launch_bounds__(256)
transpose_k(const float* __restrict__ src, float* __restrict__ dst)
{
    __shared__ float t[32][33];
    const int s0 = blockIdx.x << 5;
    const int d0 = blockIdx.y << 5;
    const int tx = threadIdx.x & 31;
    const int ty = threadIdx.x >> 5;
    const float* sp = src + (size_t)blockIdx.z * S * D;
    float*       dp = dst + (size_t)blockIdx.z * D * S;
    #pragma unroll
    for (int i = 0; i < 32; i += 8)
        t[ty + i][tx] = sp[(size_t)(s0 + ty + i) * D + d0 + tx];
    __syncthreads();
    #pragma unroll
    for (int i = 0; i < 32; i += 8)
        dp[(size_t)(d0 + ty + i) * S + s0 + tx] = t[tx][ty + i];
}

// ---------------------------------------------------------------------------
__global__ void __launch_bounds__(256)
softmax_causal(float* __restrict__ sc)
{
    const int r = blockIdx.x;
    const int b = r >> 12;
    const int i = r & (S - 1);
    float* row = sc + ((long long)b * S * S) + ((long long)i * S);
    const int n  = i + 1;
    const int n4 = n & ~3;
    const int tid  = threadIdx.x;
    const int wid  = tid >> 5;
    const int lane = tid & 31;
    const float scale = 0.03125f;   // 1/sqrt(1024)

    __shared__ float shm[8], shs[8];

    auto upd = [&](float& m, float& s, float v) {
        if (v <= m) s += __expf((v - m) * scale);
        else { s = s * __expf((m - v) * scale) + 1.f; m = v; }
    };

    float m = -3.0e38f, s = 0.f;
    for (int j = tid * 4; j < n4; j += 1024) {
        float4 vv = *(const float4*)(row + j);
        upd(m, s, vv.x); upd(m, s, vv.y); upd(m, s, vv.z); upd(m, s, vv.w);
    }
    for (int j = n4 + tid; j < n; j += 256) upd(m, s, row[j]);

    #pragma unroll
    for (int o = 16; o > 0; o >>= 1) {
        float mo = __shfl_xor_sync(0xffffffffu, m, o);
        float so = __shfl_xor_sync(0xffffffffu, s, o);
        float M  = fmaxf(m, mo);
        s = s * __expf((m - M) * scale) + so * __expf((mo - M) * scale);
        m = M;
    }
    if (lane == 0) { shm[wid] = m; shs[wid] = s; }
    __syncthreads();
    float M = shm[0], Sm = shs[0];
    #pragma unroll
    for (int t = 1; t < 8; t++) {
        float mo = shm[t], so = shs[t];
        float Mx = fmaxf(M, mo);
        Sm = Sm * __expf((M - Mx) * scale) + so * __expf((mo - Mx) * scale);
        M = Mx;
    }
    const float inv = 1.0f / Sm;

    for (int j = tid * 4; j < n4; j += 1024) {
        float4 vv = *(const float4*)(row + j);
        vv.x = __expf((vv.x - M) * scale) * inv;
        vv.y = __expf((vv.y - M) * scale) * inv;
        vv.z = __expf((vv.z - M) * scale) * inv;
        vv.w = __expf((vv.w - M) * scale) * inv;
        *(float4*)(row + j) = vv;
    }
    for (int j = n4 + tid; j < n; j += 256)
        row[j] = __expf((row[j] - M) * scale) * inv;

    const int end = ((i >> 7) + 1) << 7;
    for (int j = n + tid; j < end; j += 256) row[j] = 0.f;
}

// ---------------------------------------------------------------------------
extern "C" void kernel_launch(void* const* d_in, const int* in_sizes, int n_in,
                              void* d_out, int out_size)
{
    const float* x  = (const float*)d_in[0];
    const float* Wq = (const float*)d_in[1];
    const float* Wk = (const float*)d_in[2];
    const float* Wv = (const float*)d_in[3];
    float* out = (float*)d_out;

    static float *q = nullptr, *k = nullptr, *kt = nullptr, *v = nullptr,
                 *sc = nullptr;
    static bool init = false;
    if (!init) {
        cudaGetSymbolAddress((void**)&q,  g_q);
        cudaGetSymbolAddress((void**)&k,  g_k);
        cudaGetSymbolAddress((void**)&kt, g_kt);
        cudaGetSymbolAddress((void**)&v,  g_v);
        cudaGetSymbolAddress((void**)&sc, g_s);
        cudaFuncSetAttribute(gemm_qkv,
                             cudaFuncAttributeMaxDynamicSharedMemorySize, SMEM_BYTES);
        cudaFuncSetAttribute(gemm_scores,
                             cudaFuncAttributeMaxDynamicSharedMemorySize, SMEM_BYTES);
        cudaFuncSetAttribute(gemm_pv,
                             cudaFuncAttributeMaxDynamicSharedMemorySize, SMEM_BYTES);
        init = true;
    }

    gemm_qkv<<<dim3(D / BN, (Bb * S) / BM, 3), 512, SMEM_BYTES>>>(
        x, Wq, Wk, Wv, q, k, v);
    transpose_k<<<dim3(S / 32, D / 32, Bb), 256>>>(k, kt);
    gemm_scores<<<dim3(S / BN, S / BM, Bb), 512, SMEM_BYTES>>>(q, kt, sc);
    softmax_causal<<<Bb * S, 256>>>(sc);
    gemm_pv<<<dim3(D / BN, S / BM, Bb), 512, SMEM_BYTES>>>(sc, v, out);
}

// round 7
// speedup vs baseline: 1.4258x; 1.4190x over previous
#include <cuda_runtime.h>
#include <cstdint>

// ============================================================================
// CausalAttention, B=4, S=4096, D=1024, fp32 in/out.
// bf16x3-split mma.sync m16n8k16 GEMMs (hi/lo bf16x2 tiles pre-split in
// swizzled smem, fp32 accumulate; terms hh + lh + hl). 256 thr/CTA, 4x2 warp
// grid, 32x64 warp tiles, double-buffered smem, register prefetch, one
// __syncthreads per 32-K chunk. tcgen05 is unavailable on this build target
// (ptxas rejects it for sm_103), so this maxes the mma.sync path.
// ============================================================================

static constexpr int Bb = 4;
static constexpr int S  = 4096;
static constexpr int D  = 1024;
static constexpr int BM = 128;
static constexpr int BN = 128;
static constexpr int BK = 32;                 // floats per chunk = 16 bf16x2 words

// tile = 128 rows x 16 words, "pair-line" swizzled: 2 rows per 32-word line
static constexpr int TILE_W    = 2048;        // words (8 KB)
static constexpr int STAGE_W   = 4 * TILE_W;  // Ah, Al, Bh, Bl
static constexpr int SMEM_BYTES = 2 * STAGE_W * 4;   // 65536

static __device__ float g_q [(size_t)Bb * S * D];
static __device__ float g_k [(size_t)Bb * S * D];
static __device__ float g_v [(size_t)Bb * S * D];
static __device__ float g_vt[(size_t)Bb * D * S];
static __device__ float g_wt[(size_t)3 * D * D];
static __device__ float g_s [(size_t)Bb * S * S];

// ---------------------------------------------------------------------------
// swizzled word index of (row, w) inside a [128][16] tile
__device__ __forceinline__ uint32_t tile_addr(uint32_t row, uint32_t w) {
    const uint32_t line = row >> 1;
    const uint32_t off  = ((row & 1u) << 4) + w;
    return line * 32u + (off ^ ((line & 7u) << 2));
}

// split (x0, x1) into hi/lo bf16x2 words (lower 16 bits = x0)
__device__ __forceinline__ void bf16_split2(float x0, float x1,
                                            uint32_t& hw, uint32_t& lw) {
    asm("cvt.rn.bf16x2.f32 %0, %1, %2;" : "=r"(hw) : "f"(x1), "f"(x0));
    const float h0 = __uint_as_float(hw << 16);
    const float h1 = __uint_as_float(hw & 0xffff0000u);
    const float r0 = x0 - h0;
    const float r1 = x1 - h1;
    asm("cvt.rn.bf16x2.f32 %0, %1, %2;" : "=r"(lw) : "f"(r1), "f"(r0));
}

__device__ __forceinline__ void mma_bf16(float (&d)[4], const uint32_t (&a)[4],
                                         const uint32_t (&b)[2]) {
    asm("mma.sync.aligned.m16n8k16.row.col.f32.bf16.bf16.f32 "
        "{%0,%1,%2,%3}, {%4,%5,%6,%7}, {%8,%9}, {%0,%1,%2,%3};"
        : "+f"(d[0]), "+f"(d[1]), "+f"(d[2]), "+f"(d[3])
        : "r"(a[0]), "r"(a[1]), "r"(a[2]), "r"(a[3]), "r"(b[0]), "r"(b[1]));
}

// convert 4 float4 (16 floats of one row-half) -> 8 hi + 8 lo words, store as
// two uint4 each at swizzled quad addresses i0, i0^4.
__device__ __forceinline__ void stage_half(uint32_t* hiT, uint32_t* loT,
                                           uint32_t i0, const float4 f[4]) {
    uint4 h0, h1, l0, l1;
    bf16_split2(f[0].x, f[0].y, h0.x, l0.x);
    bf16_split2(f[0].z, f[0].w, h0.y, l0.y);
    bf16_split2(f[1].x, f[1].y, h0.z, l0.z);
    bf16_split2(f[1].z, f[1].w, h0.w, l0.w);
    bf16_split2(f[2].x, f[2].y, h1.x, l1.x);
    bf16_split2(f[2].z, f[2].w, h1.y, l1.y);
    bf16_split2(f[3].x, f[3].y, h1.z, l1.z);
    bf16_split2(f[3].z, f[3].w, h1.w, l1.w);
    *(uint4*)(hiT + i0)        = h0;
    *(uint4*)(hiT + (i0 ^ 4u)) = h1;
    *(uint4*)(loT + i0)        = l0;
    *(uint4*)(loT + (i0 ^ 4u)) = l1;
}

// ---------------------------------------------------------------------------
// C[bm,bn tile] = A(MxK, lda, row-major) * B^T, B is [N,K] row-major (ldb).
// 256 threads. KLIM: K limited to (bm+1)*BM.
// ---------------------------------------------------------------------------
template<bool KLIM>
__device__ __forceinline__ void
gemm_core(const float* __restrict__ A, const float* __restrict__ Bm,
          float* __restrict__ C, int N, int K, int lda, int ldb,
          int bm, int bn)
{
    const int kEnd = KLIM ? min(K, (bm + 1) * BM) : K;

    extern __shared__ uint32_t sm[];

    const int tid  = threadIdx.x;
    const int wid  = tid >> 5;
    const int wm   = wid & 3;               // 4 warps along M
    const int wn   = wid >> 2;              // 2 warps along N
    const int lane = tid & 31;
    const int g    = lane >> 2;
    const int c    = lane & 3;

    // staging map: thread t -> row t>>1, k-half h = t&1 (16 floats)
    const int srow = tid >> 1;
    const int h    = tid & 1;
    const uint32_t stA = tile_addr(srow, h * 8);   // quad-aligned
    const float* Ap = A + (long long)(bm * BM + srow) * lda + h * 16;
    const float* Bp = Bm + (long long)(bn * BN + srow) * ldb + h * 16;

    float4 pa[4], pb[4];
    #pragma unroll
    for (int i = 0; i < 4; i++) {
        pa[i] = *(const float4*)(Ap + i * 4);
        pb[i] = *(const float4*)(Bp + i * 4);
    }

    {   // stage 0
        uint32_t* Ah = sm;
        uint32_t* Al = sm + TILE_W;
        uint32_t* Bh = sm + 2 * TILE_W;
        uint32_t* Bl = sm + 3 * TILE_W;
        stage_half(Ah, Al, stA, pa);
        stage_half(Bh, Bl, stA, pb);
    }
    __syncthreads();

    // fragment base indices (word addr of (row, kp=c))
    uint32_t aB[2][2], bB[8];
    #pragma unroll
    for (int mi = 0; mi < 2; mi++) {
        const uint32_t r = wm * 32 + mi * 16 + g;
        aB[mi][0] = tile_addr(r, c);
        aB[mi][1] = tile_addr(r + 8, c);
    }
    #pragma unroll
    for (int ni = 0; ni < 8; ni++)
        bB[ni] = tile_addr(wn * 64 + ni * 8 + g, c);

    float acc[2][8][4];
    #pragma unroll
    for (int mi = 0; mi < 2; mi++)
        #pragma unroll
        for (int ni = 0; ni < 8; ni++)
            #pragma unroll
            for (int q = 0; q < 4; q++) acc[mi][ni][q] = 0.f;

    int st = 0;
    for (int k0 = 0; k0 < kEnd; k0 += BK) {
        const bool has_next = (k0 + BK) < kEnd;
        if (has_next) {
            #pragma unroll
            for (int i = 0; i < 4; i++) {
                pa[i] = *(const float4*)(Ap + (k0 + BK) + i * 4);
                pb[i] = *(const float4*)(Bp + (k0 + BK) + i * 4);
            }
        }

        const uint32_t* Ah = sm + st * STAGE_W;
        const uint32_t* Al = Ah + TILE_W;
        const uint32_t* Bh = Ah + 2 * TILE_W;
        const uint32_t* Bl = Ah + 3 * TILE_W;

        #pragma unroll
        for (int kt = 0; kt < 2; kt++) {      // two k16 steps per chunk
            const uint32_t kx = kt * 8;        // toggles bit 3 of swizzled idx

            uint32_t ah[2][4], al[2][4];
            #pragma unroll
            for (int mi = 0; mi < 2; mi++) {
                const uint32_t i0 = aB[mi][0] ^ kx;
                const uint32_t i1 = aB[mi][1] ^ kx;
                ah[mi][0] = Ah[i0];       al[mi][0] = Al[i0];
                ah[mi][1] = Ah[i1];       al[mi][1] = Al[i1];
                ah[mi][2] = Ah[i0 ^ 4u];  al[mi][2] = Al[i0 ^ 4u];
                ah[mi][3] = Ah[i1 ^ 4u];  al[mi][3] = Al[i1 ^ 4u];
            }
            uint32_t bh[8][2], bl[8][2];
            #pragma unroll
            for (int ni = 0; ni < 8; ni++) {
                const uint32_t i0 = bB[ni] ^ kx;
                bh[ni][0] = Bh[i0];       bh[ni][1] = Bh[i0 ^ 4u];
                bl[ni][0] = Bl[i0];       bl[ni][1] = Bl[i0 ^ 4u];
            }

            // grouped by split term; consecutive MMAs hit distinct accs
            #pragma unroll
            for (int mi = 0; mi < 2; mi++)
                #pragma unroll
                for (int ni = 0; ni < 8; ni++)
                    mma_bf16(acc[mi][ni], ah[mi], bh[ni]);
            #pragma unroll
            for (int mi = 0; mi < 2; mi++)
                #pragma unroll
                for (int ni = 0; ni < 8; ni++)
                    mma_bf16(acc[mi][ni], al[mi], bh[ni]);
            #pragma unroll
            for (int mi = 0; mi < 2; mi++)
                #pragma unroll
                for (int ni = 0; ni < 8; ni++)
                    mma_bf16(acc[mi][ni], ah[mi], bl[ni]);
        }

        if (has_next) {
            uint32_t* nAh = sm + (st ^ 1) * STAGE_W;
            uint32_t* nAl = nAh + TILE_W;
            uint32_t* nBh = nAh + 2 * TILE_W;
            uint32_t* nBl = nAh + 3 * TILE_W;
            stage_half(nAh, nAl, stA, pa);
            stage_half(nBh, nBl, stA, pb);
        }
        __syncthreads();
        st ^= 1;
    }

    // epilogue
    #pragma unroll
    for (int mi = 0; mi < 2; mi++) {
        const int r0 = bm * BM + wm * 32 + mi * 16 + g;
        #pragma unroll
        for (int ni = 0; ni < 8; ni++) {
            const int cc = bn * BN + wn * 64 + ni * 8 + c * 2;
            float2 v0 = make_float2(acc[mi][ni][0], acc[mi][ni][1]);
            float2 v1 = make_float2(acc[mi][ni][2], acc[mi][ni][3]);
            *(float2*)(C + (long long)r0 * N + cc)       = v0;
            *(float2*)(C + (long long)(r0 + 8) * N + cc) = v1;
        }
    }
}

// ---- kernels ---------------------------------------------------------------
__global__ void __launch_bounds__(256, 1)
k_qkv(const float* __restrict__ x, const float* __restrict__ wt,
      float* __restrict__ q, float* __restrict__ k, float* __restrict__ v)
{
    const float* W = wt + (size_t)blockIdx.z * D * D;   // W^T: [d_out][d_in]
    float* out = blockIdx.z == 0 ? q : (blockIdx.z == 1 ? k : v);
    gemm_core<false>(x, W, out, D, D, D, D, blockIdx.y, blockIdx.x);
}

__global__ void __launch_bounds__(256, 1)
k_scores(const float* __restrict__ q, const float* __restrict__ kk,
         float* __restrict__ sc)
{
    if ((int)blockIdx.x > (int)blockIdx.y) return;      // causal block skip
    const size_t z = blockIdx.z;
    gemm_core<false>(q + z * (size_t)S * D, kk + z * (size_t)S * D,
                     sc + z * (size_t)S * S, S, D, D, D, blockIdx.y, blockIdx.x);
}

__global__ void __launch_bounds__(256, 1)
k_pv(const float* __restrict__ sc, const float* __restrict__ vt,
     float* __restrict__ out)
{
    const size_t z = blockIdx.z;
    gemm_core<true>(sc + z * (size_t)S * S, vt + z * (size_t)D * S,
                    out + z * (size_t)S * D, D, S, S, S,
                    blockIdx.y, blockIdx.x);
}

// ---- transposes ------------------------------------------------------------
__global__ void __launch_bounds__(256)
k_wt(const float* __restrict__ wq, const float* __restrict__ wk,
     const float* __restrict__ wv, float* __restrict__ wt)
{
    __shared__ float t[32][33];
    const float* src = blockIdx.z == 0 ? wq : (blockIdx.z == 1 ? wk : wv);
    float* dst = wt + (size_t)blockIdx.z * D * D;
    const int r0 = blockIdx.x << 5, c0 = blockIdx.y << 5;
    const int tx = threadIdx.x & 31, ty = threadIdx.x >> 5;
    #pragma unroll
    for (int i = 0; i < 32; i += 8)
        t[ty + i][tx] = src[(size_t)(r0 + ty + i) * D + c0 + tx];
    __syncthreads();
    #pragma unroll
    for (int i = 0; i < 32; i += 8)
        dst[(size_t)(c0 + ty + i) * D + r0 + tx] = t[tx][ty + i];
}

__global__ void __launch_bounds__(256)
k_vt(const float* __restrict__ v, float* __restrict__ vt)
{
    __shared__ float t[32][33];
    const float* sp = v  + (size_t)blockIdx.z * S * D;
    float*       dp = vt + (size_t)blockIdx.z * D * S;
    const int s0 = blockIdx.x << 5, d0 = blockIdx.y << 5;
    const int tx = threadIdx.x & 31, ty = threadIdx.x >> 5;
    #pragma unroll
    for (int i = 0; i < 32; i += 8)
        t[ty + i][tx] = sp[(size_t)(s0 + ty + i) * D + d0 + tx];
    __syncthreads();
    #pragma unroll
    for (int i = 0; i < 32; i += 8)
        dp[(size_t)(d0 + ty + i) * S + s0 + tx] = t[tx][ty + i];
}

// ---- softmax ---------------------------------------------------------------
__global__ void __launch_bounds__(256)
softmax_causal(float* __restrict__ sc)
{
    const int r = blockIdx.x;
    const int b = r >> 12;
    const int i = r & (S - 1);
    float* row = sc + ((long long)b * S * S) + ((long long)i * S);
    const int n  = i + 1;
    const int n4 = n & ~3;
    const int tid  = threadIdx.x;
    const int wid  = tid >> 5;
    const int lane = tid & 31;
    const float scale = 0.03125f;   // 1/sqrt(1024)

    __shared__ float shm[8], shs[8];

    auto upd = [&](float& m, float& s, float v) {
        if (v <= m) s += __expf((v - m) * scale);
        else { s = s * __expf((m - v) * scale) + 1.f; m = v; }
    };

    float m = -3.0e38f, s = 0.f;
    for (int j = tid * 4; j < n4; j += 1024) {
        float4 vv = *(const float4*)(row + j);
        upd(m, s, vv.x); upd(m, s, vv.y); upd(m, s, vv.z); upd(m, s, vv.w);
    }
    for (int j = n4 + tid; j < n; j += 256) upd(m, s, row[j]);

    #pragma unroll
    for (int o = 16; o > 0; o >>= 1) {
        float mo = __shfl_xor_sync(0xffffffffu, m, o);
        float so = __shfl_xor_sync(0xffffffffu, s, o);
        float M  = fmaxf(m, mo);
        s = s * __expf((m - M) * scale) + so * __expf((mo - M) * scale);
        m = M;
    }
    if (lane == 0) { shm[wid] = m; shs[wid] = s; }
    __syncthreads();
    float M = shm[0], Sm = shs[0];
    #pragma unroll
    for (int t = 1; t < 8; t++) {
        float mo = shm[t], so = shs[t];
        float Mx = fmaxf(M, mo);
        Sm = Sm * __expf((M - Mx) * scale) + so * __expf((mo - Mx) * scale);
        M = Mx;
    }
    const float inv = 1.0f / Sm;

    for (int j = tid * 4; j < n4; j += 1024) {
        float4 vv = *(const float4*)(row + j);
        vv.x = __expf((vv.x - M) * scale) * inv;
        vv.y = __expf((vv.y - M) * scale) * inv;
        vv.z = __expf((vv.z - M) * scale) * inv;
        vv.w = __expf((vv.w - M) * scale) * inv;
        *(float4*)(row + j) = vv;
    }
    for (int j = n4 + tid; j < n; j += 256)
        row[j] = __expf((row[j] - M) * scale) * inv;

    const int end = ((i >> 7) + 1) << 7;
    for (int j = n + tid; j < end; j += 256) row[j] = 0.f;
}

// ---------------------------------------------------------------------------
extern "C" void kernel_launch(void* const* d_in, const int* in_sizes, int n_in,
                              void* d_out, int out_size)
{
    const float* x  = (const float*)d_in[0];
    const float* Wq = (const float*)d_in[1];
    const float* Wk = (const float*)d_in[2];
    const float* Wv = (const float*)d_in[3];
    float* out = (float*)d_out;

    static float *q = nullptr, *k = nullptr, *v = nullptr, *vt = nullptr,
                 *wt = nullptr, *sc = nullptr;
    static bool init = false;
    if (!init) {
        cudaGetSymbolAddress((void**)&q,  g_q);
        cudaGetSymbolAddress((void**)&k,  g_k);
        cudaGetSymbolAddress((void**)&v,  g_v);
        cudaGetSymbolAddress((void**)&vt, g_vt);
        cudaGetSymbolAddress((void**)&wt, g_wt);
        cudaGetSymbolAddress((void**)&sc, g_s);
        cudaFuncSetAttribute(k_qkv,
                             cudaFuncAttributeMaxDynamicSharedMemorySize, SMEM_BYTES);
        cudaFuncSetAttribute(k_scores,
                             cudaFuncAttributeMaxDynamicSharedMemorySize, SMEM_BYTES);
        cudaFuncSetAttribute(k_pv,
                             cudaFuncAttributeMaxDynamicSharedMemorySize, SMEM_BYTES);
        init = true;
    }

    // 1) W^T (B operand is [N,K] = [d_out][d_in])
    k_wt<<<dim3(D / 32, D / 32, 3), 256>>>(Wq, Wk, Wv, wt);

    // 2) QKV projections
    k_qkv<<<dim3(D / BN, (Bb * S) / BM, 3), 256, SMEM_BYTES>>>(x, wt, q, k, v);

    // 3) V^T for PV
    k_vt<<<dim3(S / 32, D / 32, Bb), 256>>>(v, vt);

    // 4) scores = Q K^T  (K's natural [S,D] layout is the [N,K] operand)
    k_scores<<<dim3(S / BN, S / BM, Bb), 256, SMEM_BYTES>>>(q, k, sc);

    // 5) softmax
    softmax_causal<<<Bb * S, 256>>>(sc);

    // 6) out = P V  (B = V^T)
    k_pv<<<dim3(D / BN, S / BM, Bb), 256, SMEM_BYTES>>>(sc, vt, out);
}

// round 8
// speedup vs baseline: 1.6959x; 1.1894x over previous
#include <cuda_runtime.h>
#include <cstdint>

// ============================================================================
// CausalAttention, B=4, S=4096, D=1024, fp32 in/out.
// bf16x3-split mma.sync m16n8k16 GEMMs; hi/lo bf16x2 tiles pre-split into
// pair-line swizzled smem; fragments loaded via ldmatrix.x4 (12 LDSM per
// k16-step instead of 48 LDS.32). 256 thr/CTA, 4x2 warps, 32x64 warp tiles,
// double-buffered smem, register prefetch, one __syncthreads per 32-K chunk.
// ============================================================================

static constexpr int Bb = 4;
static constexpr int S  = 4096;
static constexpr int D  = 1024;
static constexpr int BM = 128;
static constexpr int BN = 128;
static constexpr int BK = 32;                 // floats per chunk (16 words)

static constexpr int TILE_W    = 2048;        // words per [128][16] tile (8 KB)
static constexpr int STAGE_W   = 4 * TILE_W;  // Ah, Al, Bh, Bl
static constexpr int SMEM_BYTES = 2 * STAGE_W * 4;   // 65536

static __device__ float g_q [(size_t)Bb * S * D];
static __device__ float g_k [(size_t)Bb * S * D];
static __device__ float g_v [(size_t)Bb * S * D];
static __device__ float g_vt[(size_t)Bb * D * S];
static __device__ float g_wt[(size_t)3 * D * D];
static __device__ float g_s [(size_t)Bb * S * S];

// ---------------------------------------------------------------------------
// swizzled word index of (row, w) inside a [128][16]-word tile
__device__ __forceinline__ uint32_t tile_addr(uint32_t row, uint32_t w) {
    const uint32_t line = row >> 1;
    const uint32_t off  = ((row & 1u) << 4) + w;
    return line * 32u + (off ^ ((line & 7u) << 2));
}

__device__ __forceinline__ uint32_t smem_u32(const void* p) {
    uint32_t a;
    asm("{ .reg .u64 t; cvta.to.shared.u64 t, %1; cvt.u32.u64 %0, t; }"
        : "=r"(a) : "l"(p));
    return a;
}

__device__ __forceinline__ void ldsm_x4(uint32_t (&r)[4], uint32_t saddr) {
    asm volatile("ldmatrix.sync.aligned.m8n8.x4.shared.b16 {%0,%1,%2,%3}, [%4];"
                 : "=r"(r[0]), "=r"(r[1]), "=r"(r[2]), "=r"(r[3])
                 : "r"(saddr));
}

// split (x0, x1) into hi/lo bf16x2 words (lower 16 bits = x0)
__device__ __forceinline__ void bf16_split2(float x0, float x1,
                                            uint32_t& hw, uint32_t& lw) {
    asm("cvt.rn.bf16x2.f32 %0, %1, %2;" : "=r"(hw) : "f"(x1), "f"(x0));
    const float h0 = __uint_as_float(hw << 16);
    const float h1 = __uint_as_float(hw & 0xffff0000u);
    const float r0 = x0 - h0;
    const float r1 = x1 - h1;
    asm("cvt.rn.bf16x2.f32 %0, %1, %2;" : "=r"(lw) : "f"(r1), "f"(r0));
}

__device__ __forceinline__ void mma_bf16(float (&d)[4], const uint32_t (&a)[4],
                                         uint32_t b0, uint32_t b1) {
    asm("mma.sync.aligned.m16n8k16.row.col.f32.bf16.bf16.f32 "
        "{%0,%1,%2,%3}, {%4,%5,%6,%7}, {%8,%9}, {%0,%1,%2,%3};"
        : "+f"(d[0]), "+f"(d[1]), "+f"(d[2]), "+f"(d[3])
        : "r"(a[0]), "r"(a[1]), "r"(a[2]), "r"(a[3]), "r"(b0), "r"(b1));
}

// 16 floats of one row-half -> 8 hi + 8 lo words at swizzled quads i0, i0^4
__device__ __forceinline__ void stage_half(uint32_t* hiT, uint32_t* loT,
                                           uint32_t i0, const float4 f[4]) {
    uint4 h0, h1, l0, l1;
    bf16_split2(f[0].x, f[0].y, h0.x, l0.x);
    bf16_split2(f[0].z, f[0].w, h0.y, l0.y);
    bf16_split2(f[1].x, f[1].y, h0.z, l0.z);
    bf16_split2(f[1].z, f[1].w, h0.w, l0.w);
    bf16_split2(f[2].x, f[2].y, h1.x, l1.x);
    bf16_split2(f[2].z, f[2].w, h1.y, l1.y);
    bf16_split2(f[3].x, f[3].y, h1.z, l1.z);
    bf16_split2(f[3].z, f[3].w, h1.w, l1.w);
    *(uint4*)(hiT + i0)        = h0;
    *(uint4*)(hiT + (i0 ^ 4u)) = h1;
    *(uint4*)(loT + i0)        = l0;
    *(uint4*)(loT + (i0 ^ 4u)) = l1;
}

// ---------------------------------------------------------------------------
// C[bm,bn tile] = A(MxK, lda, row-major) * B^T, B is [N,K] row-major (ldb).
// 256 threads. KLIM: K limited to (bm+1)*BM.
// ---------------------------------------------------------------------------
template<bool KLIM>
__device__ __forceinline__ void
gemm_core(const float* __restrict__ A, const float* __restrict__ Bm,
          float* __restrict__ C, int N, int K, int lda, int ldb,
          int bm, int bn)
{
    const int kEnd = KLIM ? min(K, (bm + 1) * BM) : K;

    extern __shared__ uint32_t sm[];
    const uint32_t smb = smem_u32(sm);

    const int tid  = threadIdx.x;
    const int wid  = tid >> 5;
    const int wm   = wid & 3;               // 4 warps along M
    const int wn   = wid >> 2;              // 2 warps along N
    const int lane = tid & 31;
    const int g    = lane >> 2;
    const int c    = lane & 3;
    const int l8   = lane & 7;
    const int lm   = lane >> 3;             // ldmatrix matrix id 0..3

    // ldmatrix byte addresses (relative to tile base), per kt
    // A x4 (mi): m0=rows0-7/w0-3, m1=rows8-15/w0-3, m2=rows0-7/w4-7, m3=rows8-15/w4-7
    uint32_t relA[2][2], relB[4][2];
    #pragma unroll
    for (int mi = 0; mi < 2; mi++) {
        const uint32_t row = wm * 32 + mi * 16 + ((lm & 1) << 3) + l8;
        const uint32_t w   = (lm >> 1) << 2;
        relA[mi][0] = tile_addr(row, w) * 4u;
        relA[mi][1] = tile_addr(row, w + 8) * 4u;
    }
    // B x4 (pair p): m0=n rows(2p)*8/w0-3, m1=same rows/w4-7,
    //                m2=n rows(2p+1)*8/w0-3, m3=same rows/w4-7
    #pragma unroll
    for (int p = 0; p < 4; p++) {
        const uint32_t row = wn * 64 + p * 16 + ((lm >> 1) << 3) + l8;
        const uint32_t w   = (lm & 1) << 2;
        relB[p][0] = tile_addr(row, w) * 4u;
        relB[p][1] = tile_addr(row, w + 8) * 4u;
    }

    // staging map: thread t -> row t>>1, k-half h = t&1 (16 floats)
    const int srow = tid >> 1;
    const int h    = tid & 1;
    const uint32_t stA = tile_addr(srow, h * 8);   // quad-aligned word index
    const float* Ap = A + (long long)(bm * BM + srow) * lda + h * 16;
    const float* Bp = Bm + (long long)(bn * BN + srow) * ldb + h * 16;

    float4 pa[4], pb[4];
    #pragma unroll
    for (int i = 0; i < 4; i++) {
        pa[i] = *(const float4*)(Ap + i * 4);
        pb[i] = *(const float4*)(Bp + i * 4);
    }

    {   // stage 0
        stage_half(sm,              sm + TILE_W,     stA, pa);
        stage_half(sm + 2 * TILE_W, sm + 3 * TILE_W, stA, pb);
    }
    __syncthreads();

    float acc[2][8][4];
    #pragma unroll
    for (int mi = 0; mi < 2; mi++)
        #pragma unroll
        for (int ni = 0; ni < 8; ni++)
            #pragma unroll
            for (int q = 0; q < 4; q++) acc[mi][ni][q] = 0.f;

    int st = 0;
    for (int k0 = 0; k0 < kEnd; k0 += BK) {
        const bool has_next = (k0 + BK) < kEnd;
        if (has_next) {
            #pragma unroll
            for (int i = 0; i < 4; i++) {
                pa[i] = *(const float4*)(Ap + (k0 + BK) + i * 4);
                pb[i] = *(const float4*)(Bp + (k0 + BK) + i * 4);
            }
        }

        const uint32_t bAh = smb + st * (STAGE_W * 4);
        const uint32_t bAl = bAh + TILE_W * 4;
        const uint32_t bBh = bAh + 2 * (TILE_W * 4);
        const uint32_t bBl = bAh + 3 * (TILE_W * 4);

        #pragma unroll
        for (int kt = 0; kt < 2; kt++) {
            uint32_t ah[2][4], al[2][4], bh[4][4], bl[4][4];
            #pragma unroll
            for (int mi = 0; mi < 2; mi++) {
                ldsm_x4(ah[mi], bAh + relA[mi][kt]);
                ldsm_x4(al[mi], bAl + relA[mi][kt]);
            }
            #pragma unroll
            for (int p = 0; p < 4; p++) {
                ldsm_x4(bh[p], bBh + relB[p][kt]);
                ldsm_x4(bl[p], bBl + relB[p][kt]);
            }

            // grouped by split term; consecutive MMAs hit distinct accs
            #pragma unroll
            for (int mi = 0; mi < 2; mi++)
                #pragma unroll
                for (int ni = 0; ni < 8; ni++)
                    mma_bf16(acc[mi][ni], ah[mi],
                             bh[ni >> 1][(ni & 1) * 2],
                             bh[ni >> 1][(ni & 1) * 2 + 1]);
            #pragma unroll
            for (int mi = 0; mi < 2; mi++)
                #pragma unroll
                for (int ni = 0; ni < 8; ni++)
                    mma_bf16(acc[mi][ni], al[mi],
                             bh[ni >> 1][(ni & 1) * 2],
                             bh[ni >> 1][(ni & 1) * 2 + 1]);
            #pragma unroll
            for (int mi = 0; mi < 2; mi++)
                #pragma unroll
                for (int ni = 0; ni < 8; ni++)
                    mma_bf16(acc[mi][ni], ah[mi],
                             bl[ni >> 1][(ni & 1) * 2],
                             bl[ni >> 1][(ni & 1) * 2 + 1]);
        }

        if (has_next) {
            uint32_t* nS = sm + (st ^ 1) * STAGE_W;
            stage_half(nS,              nS + TILE_W,     stA, pa);
            stage_half(nS + 2 * TILE_W, nS + 3 * TILE_W, stA, pb);
        }
        __syncthreads();
        st ^= 1;
    }

    // epilogue
    #pragma unroll
    for (int mi = 0; mi < 2; mi++) {
        const int r0 = bm * BM + wm * 32 + mi * 16 + g;
        #pragma unroll
        for (int ni = 0; ni < 8; ni++) {
            const int cc = bn * BN + wn * 64 + ni * 8 + c * 2;
            float2 v0 = make_float2(acc[mi][ni][0], acc[mi][ni][1]);
            float2 v1 = make_float2(acc[mi][ni][2], acc[mi][ni][3]);
            *(float2*)(C + (long long)r0 * N + cc)       = v0;
            *(float2*)(C + (long long)(r0 + 8) * N + cc) = v1;
        }
    }
}

// ---- kernels ---------------------------------------------------------------
__global__ void __launch_bounds__(256, 1)
k_qkv(const float* __restrict__ x, const float* __restrict__ wt,
      float* __restrict__ q, float* __restrict__ k, float* __restrict__ v)
{
    const float* W = wt + (size_t)blockIdx.z * D * D;   // W^T: [d_out][d_in]
    float* out = blockIdx.z == 0 ? q : (blockIdx.z == 1 ? k : v);
    gemm_core<false>(x, W, out, D, D, D, D, blockIdx.y, blockIdx.x);
}

__global__ void __launch_bounds__(256, 1)
k_scores(const float* __restrict__ q, const float* __restrict__ kk,
         float* __restrict__ sc)
{
    if ((int)blockIdx.x > (int)blockIdx.y) return;      // causal block skip
    const size_t z = blockIdx.z;
    gemm_core<false>(q + z * (size_t)S * D, kk + z * (size_t)S * D,
                     sc + z * (size_t)S * S, S, D, D, D, blockIdx.y, blockIdx.x);
}

__global__ void __launch_bounds__(256, 1)
k_pv(const float* __restrict__ sc, const float* __restrict__ vt,
     float* __restrict__ out)
{
    const size_t z = blockIdx.z;
    gemm_core<true>(sc + z * (size_t)S * S, vt + z * (size_t)D * S,
                    out + z * (size_t)S * D, D, S, S, S,
                    blockIdx.y, blockIdx.x);
}

// ---- transposes ------------------------------------------------------------
__global__ void __launch_bounds__(256)
k_wt(const float* __restrict__ wq, const float* __restrict__ wk,
     const float* __restrict__ wv, float* __restrict__ wt)
{
    __shared__ float t[32][33];
    const float* src = blockIdx.z == 0 ? wq : (blockIdx.z == 1 ? wk : wv);
    float* dst = wt + (size_t)blockIdx.z * D * D;
    const int r0 = blockIdx.x << 5, c0 = blockIdx.y << 5;
    const int tx = threadIdx.x & 31, ty = threadIdx.x >> 5;
    #pragma unroll
    for (int i = 0; i < 32; i += 8)
        t[ty + i][tx] = src[(size_t)(r0 + ty + i) * D + c0 + tx];
    __syncthreads();
    #pragma unroll
    for (int i = 0; i < 32; i += 8)
        dst[(size_t)(c0 + ty + i) * D + r0 + tx] = t[tx][ty + i];
}

__global__ void __launch_bounds__(256)
k_vt(const float* __restrict__ v, float* __restrict__ vt)
{
    __shared__ float t[32][33];
    const float* sp = v  + (size_t)blockIdx.z * S * D;
    float*       dp = vt + (size_t)blockIdx.z * D * S;
    const int s0 = blockIdx.x << 5, d0 = blockIdx.y << 5;
    const int tx = threadIdx.x & 31, ty = threadIdx.x >> 5;
    #pragma unroll
    for (int i = 0; i < 32; i += 8)
        t[ty + i][tx] = sp[(size_t)(s0 + ty + i) * D + d0 + tx];
    __syncthreads();
    #pragma unroll
    for (int i = 0; i < 32; i += 8)
        dp[(size_t)(d0 + ty + i) * S + s0 + tx] = t[tx][ty + i];
}

// ---- softmax ---------------------------------------------------------------
__global__ void __launch_bounds__(256)
softmax_causal(float* __restrict__ sc)
{
    const int r = blockIdx.x;
    const int b = r >> 12;
    const int i = r & (S - 1);
    float* row = sc + ((long long)b * S * S) + ((long long)i * S);
    const int n  = i + 1;
    const int n4 = n & ~3;
    const int tid  = threadIdx.x;
    const int wid  = tid >> 5;
    const int lane = tid & 31;
    const float scale = 0.03125f;   // 1/sqrt(1024)

    __shared__ float shm[8], shs[8];

    auto upd = [&](float& m, float& s, float v) {
        if (v <= m) s += __expf((v - m) * scale);
        else { s = s * __expf((m - v) * scale) + 1.f; m = v; }
    };

    float m = -3.0e38f, s = 0.f;
    for (int j = tid * 4; j < n4; j += 1024) {
        float4 vv = *(const float4*)(row + j);
        upd(m, s, vv.x); upd(m, s, vv.y); upd(m, s, vv.z); upd(m, s, vv.w);
    }
    for (int j = n4 + tid; j < n; j += 256) upd(m, s, row[j]);

    #pragma unroll
    for (int o = 16; o > 0; o >>= 1) {
        float mo = __shfl_xor_sync(0xffffffffu, m, o);
        float so = __shfl_xor_sync(0xffffffffu, s, o);
        float M  = fmaxf(m, mo);
        s = s * __expf((m - M) * scale) + so * __expf((mo - M) * scale);
        m = M;
    }
    if (lane == 0) { shm[wid] = m; shs[wid] = s; }
    __syncthreads();
    float M = shm[0], Sm = shs[0];
    #pragma unroll
    for (int t = 1; t < 8; t++) {
        float mo = shm[t], so = shs[t];
        float Mx = fmaxf(M, mo);
        Sm = Sm * __expf((M - Mx) * scale) + so * __expf((mo - Mx) * scale);
        M = Mx;
    }
    const float inv = 1.0f / Sm;

    for (int j = tid * 4; j < n4; j += 1024) {
        float4 vv = *(const float4*)(row + j);
        vv.x = __expf((vv.x - M) * scale) * inv;
        vv.y = __expf((vv.y - M) * scale) * inv;
        vv.z = __expf((vv.z - M) * scale) * inv;
        vv.w = __expf((vv.w - M) * scale) * inv;
        *(float4*)(row + j) = vv;
    }
    for (int j = n4 + tid; j < n; j += 256)
        row[j] = __expf((row[j] - M) * scale) * inv;

    const int end = ((i >> 7) + 1) << 7;
    for (int j = n + tid; j < end; j += 256) row[j] = 0.f;
}

// ---------------------------------------------------------------------------
extern "C" void kernel_launch(void* const* d_in, const int* in_sizes, int n_in,
                              void* d_out, int out_size)
{
    const float* x  = (const float*)d_in[0];
    const float* Wq = (const float*)d_in[1];
    const float* Wk = (const float*)d_in[2];
    const float* Wv = (const float*)d_in[3];
    float* out = (float*)d_out;

    static float *q = nullptr, *k = nullptr, *v = nullptr, *vt = nullptr,
                 *wt = nullptr, *sc = nullptr;
    static bool init = false;
    if (!init) {
        cudaGetSymbolAddress((void**)&q,  g_q);
        cudaGetSymbolAddress((void**)&k,  g_k);
        cudaGetSymbolAddress((void**)&v,  g_v);
        cudaGetSymbolAddress((void**)&vt, g_vt);
        cudaGetSymbolAddress((void**)&wt, g_wt);
        cudaGetSymbolAddress((void**)&sc, g_s);
        cudaFuncSetAttribute(k_qkv,
                             cudaFuncAttributeMaxDynamicSharedMemorySize, SMEM_BYTES);
        cudaFuncSetAttribute(k_scores,
                             cudaFuncAttributeMaxDynamicSharedMemorySize, SMEM_BYTES);
        cudaFuncSetAttribute(k_pv,
                             cudaFuncAttributeMaxDynamicSharedMemorySize, SMEM_BYTES);
        init = true;
    }

    // 1) W^T (B operand is [N,K] = [d_out][d_in])
    k_wt<<<dim3(D / 32, D / 32, 3), 256>>>(Wq, Wk, Wv, wt);

    // 2) QKV projections
    k_qkv<<<dim3(D / BN, (Bb * S) / BM, 3), 256, SMEM_BYTES>>>(x, wt, q, k, v);

    // 3) V^T for PV
    k_vt<<<dim3(S / 32, D / 32, Bb), 256>>>(v, vt);

    // 4) scores = Q K^T  (K's natural [S,D] layout is the [N,K] operand)
    k_scores<<<dim3(S / BN, S / BM, Bb), 256, SMEM_BYTES>>>(q, k, sc);

    // 5) softmax
    softmax_causal<<<Bb * S, 256>>>(sc);

    // 6) out = P V  (B = V^T)
    k_pv<<<dim3(D / BN, S / BM, Bb), 256, SMEM_BYTES>>>(sc, vt, out);
}